// round 1
// baseline (speedup 1.0000x reference)
#include <cuda_runtime.h>
#include <cuda_bf16.h>

#define NN 50000
#define NE 800000
#define NG 128
#define F 64

// ---- scratch (static device arrays; no allocation) ----
__device__ __align__(16) float g_xp[NN * F];    // x @ W  (current layer)
__device__ __align__(16) float g_agg[NN * F];   // sum_e exp(e)*xp[src]
__device__ float g_asrc[NN];
__device__ float g_adst[NN];
__device__ float g_denom[NN];
__device__ __align__(16) float g_pool[NG * F];
__device__ int g_cnt[NG];

__device__ __forceinline__ void red_add_v4(float* addr, float a, float b, float c, float d) {
    asm volatile("red.global.add.v4.f32 [%0], {%1,%2,%3,%4};"
                 :: "l"(addr), "f"(a), "f"(b), "f"(c), "f"(d) : "memory");
}

__global__ void zero_kernel() {
    int i = blockIdx.x * blockDim.x + threadIdx.x;
    if (i < NG * F) g_pool[i] = 0.f;
    if (i < NG) g_cnt[i] = 0;
}

// Node kernel: h = (first ? x : relu(agg/denom + bias_prev)); xp = h @ W;
// asrc = xp . a_src; adst = xp . a_dst; self-loop init of agg/denom.
// 256 threads = 4 nodes (64 threads each); 4 iterations -> 16 nodes per block.
__global__ __launch_bounds__(256) void node_kernel(
    const float* __restrict__ x,          // used if first
    const float* __restrict__ W,
    const float* __restrict__ a_src,
    const float* __restrict__ a_dst,
    const float* __restrict__ bias_prev,  // used if !first
    int first)
{
    __shared__ float Wsm[F * F];
    __shared__ float hrow[4][F];
    __shared__ float red[4][4];  // [node][asrc_h0, asrc_h1, adst_h0, adst_h1]
    __shared__ float exls[4];

    int tid = threadIdx.x;
    for (int i = tid; i < F * F; i += 256) Wsm[i] = W[i];

    int j = tid >> 6;          // node slot in block (0..3)
    int f = tid & 63;          // feature
    int lane = tid & 31;
    int half = (tid >> 5) & 1;

    float as_f = a_src[f];
    float ad_f = a_dst[f];
    float bf = first ? 0.f : bias_prev[f];
    __syncthreads();

    for (int iter = 0; iter < 4; ++iter) {
        int n = blockIdx.x * 16 + iter * 4 + j;
        float h = 0.f;
        if (n < NN) {
            if (first) {
                h = x[n * F + f];
            } else {
                h = g_agg[n * F + f] / g_denom[n] + bf;
                h = fmaxf(h, 0.f);
            }
        }
        hrow[j][f] = h;
        __syncthreads();

        // xp[n][f] = sum_k h[k] * W[k][f]
        float acc = 0.f;
#pragma unroll
        for (int k = 0; k < F; ++k) acc = fmaf(hrow[j][k], Wsm[k * F + f], acc);

        // reduce acc*a_src and acc*a_dst over the 64 threads of this node
        float ps = acc * as_f;
        float pd = acc * ad_f;
#pragma unroll
        for (int o = 16; o; o >>= 1) {
            ps += __shfl_xor_sync(0xffffffffu, ps, o);
            pd += __shfl_xor_sync(0xffffffffu, pd, o);
        }
        if (lane == 0) { red[j][half] = ps; red[j][2 + half] = pd; }
        __syncthreads();

        if (f == 0 && n < NN) {
            float asn = red[j][0] + red[j][1];
            float adn = red[j][2] + red[j][3];
            g_asrc[n] = asn;
            g_adst[n] = adn;
            float e = asn + adn;               // self-loop: src == dst == n
            e = e > 0.f ? e : 0.2f * e;        // leaky relu
            float ex = expf(e);
            exls[j] = ex;
            g_denom[n] = ex;
        }
        __syncthreads();

        if (n < NN) {
            float ex = exls[j];
            g_xp[n * F + f] = acc;
            g_agg[n * F + f] = ex * acc;       // self-loop contribution
        }
        __syncthreads();
    }
}

// Edge kernel: 16 threads per edge. lane0 computes exp(leaky(asrc[s]+adst[d])),
// adds to denom[d]; all lanes scatter ex*xp[s] (float4 vector red) into agg[d].
__global__ __launch_bounds__(256) void edge_kernel(
    const int* __restrict__ src, const int* __restrict__ dst)
{
    int gid = blockIdx.x * blockDim.x + threadIdx.x;
    int e = gid >> 4;
    int lane = gid & 15;
    if (e >= NE) return;

    int s = src[e];
    int d = dst[e];

    float ex = 0.f;
    if (lane == 0) {
        float ee = g_asrc[s] + g_adst[d];
        ee = ee > 0.f ? ee : 0.2f * ee;
        ex = expf(ee);
        atomicAdd(&g_denom[d], ex);
    }
    ex = __shfl_sync(0xffffffffu, ex, 0, 16);

    const float4* xp4 = reinterpret_cast<const float4*>(g_xp);
    float4 v = xp4[s * 16 + lane];
    float* a = g_agg + (d * 16 + lane) * 4;
    red_add_v4(a, ex * v.x, ex * v.y, ex * v.z, ex * v.w);
}

// Pool: h2 = relu(agg/denom + b2); atomic-add into per-graph sums + counts.
__global__ __launch_bounds__(256) void pool_kernel(
    const float* __restrict__ bias, const int* __restrict__ batch)
{
    int gid = blockIdx.x * blockDim.x + threadIdx.x;
    int n = gid >> 4;
    int lane = gid & 15;
    if (n >= NN) return;

    float dinv = 1.f / g_denom[n];
    float4 v = reinterpret_cast<const float4*>(g_agg)[n * 16 + lane];
    float4 b = reinterpret_cast<const float4*>(bias)[lane];
    v.x = fmaxf(fmaf(v.x, dinv, b.x), 0.f);
    v.y = fmaxf(fmaf(v.y, dinv, b.y), 0.f);
    v.z = fmaxf(fmaf(v.z, dinv, b.z), 0.f);
    v.w = fmaxf(fmaf(v.w, dinv, b.w), 0.f);

    int g = batch[n];
    red_add_v4(g_pool + (g * 16 + lane) * 4, v.x, v.y, v.z, v.w);
    if (lane == 0) atomicAdd(&g_cnt[g], 1);
}

__global__ void final_kernel(float* __restrict__ out) {
    int i = blockIdx.x * blockDim.x + threadIdx.x;
    if (i >= NG * F) return;
    int g = i >> 6;
    float c = (float)max(g_cnt[g], 1);
    out[i] = g_pool[i] / c;
}

extern "C" void kernel_launch(void* const* d_in, const int* in_sizes, int n_in,
                              void* d_out, int out_size) {
    const float* x     = (const float*)d_in[0];
    const int*   ei    = (const int*)d_in[1];     // [2, NE]
    const int*   batch = (const int*)d_in[2];
    const float* W1    = (const float*)d_in[3];
    const float* as1   = (const float*)d_in[4];
    const float* ad1   = (const float*)d_in[5];
    const float* b1    = (const float*)d_in[6];
    const float* W2    = (const float*)d_in[7];
    const float* as2   = (const float*)d_in[8];
    const float* ad2   = (const float*)d_in[9];
    const float* b2    = (const float*)d_in[10];
    float* out = (float*)d_out;

    const int* src = ei;
    const int* dst = ei + NE;

    int node_blocks = (NN + 15) / 16;           // 3125
    int edge_blocks = (NE * 16 + 255) / 256;    // 50000
    int pool_blocks = (NN * 16 + 255) / 256;    // 3125

    zero_kernel<<<(NG * F + 255) / 256, 256>>>();

    // layer 1
    node_kernel<<<node_blocks, 256>>>(x, W1, as1, ad1, nullptr, 1);
    edge_kernel<<<edge_blocks, 256>>>(src, dst);

    // layer 2 (reads layer-1 agg/denom, applies b1 + relu, re-inits agg/denom)
    node_kernel<<<node_blocks, 256>>>(nullptr, W2, as2, ad2, b1, 0);
    edge_kernel<<<edge_blocks, 256>>>(src, dst);

    // readout
    pool_kernel<<<pool_blocks, 256>>>(b2, batch);
    final_kernel<<<(NG * F + 255) / 256, 256>>>(out);
}

// round 2
// speedup vs baseline: 1.2997x; 1.2997x over previous
#include <cuda_runtime.h>
#include <cuda_bf16.h>

#define NN 50000
#define NE 800000
#define NG 128
#define F 64

// ---- scratch (static device arrays; no allocation) ----
__device__ __align__(16) float g_xp[NN * F];    // x @ W  (current layer)
__device__ __align__(16) float g_agg[NN * F];   // sum_e exp(e)*xp[src]
__device__ float g_asrc[NN];
__device__ float g_adst[NN];
__device__ float g_denom[NN];
__device__ __align__(16) float g_pool[NG * F];
__device__ int g_cnt[NG];

__device__ __forceinline__ void red_add_v4(float* addr, float a, float b, float c, float d) {
    asm volatile("red.global.add.v4.f32 [%0], {%1,%2,%3,%4};"
                 :: "l"(addr), "f"(a), "f"(b), "f"(c), "f"(d) : "memory");
}

__global__ void zero_kernel() {
    int i = blockIdx.x * blockDim.x + threadIdx.x;
    if (i < NG * F) g_pool[i] = 0.f;
    if (i < NG) g_cnt[i] = 0;
}

// Node kernel (register-tiled GEMM):
// 256 threads handle 32 nodes. Thread (g = tid>>4, c = tid&15) computes
// nodes {g, g+16}, features [4c, 4c+4). Inner loop: 1 LDS.128 (W) +
// 2 broadcast LDS.32 (h) per 8 FMAs.
__global__ __launch_bounds__(256) void node_kernel(
    const float* __restrict__ x,          // used if first
    const float* __restrict__ W,
    const float* __restrict__ a_src,
    const float* __restrict__ a_dst,
    const float* __restrict__ bias_prev,  // used if !first
    int first)
{
    __shared__ float4 Wsm[F * 16];   // [k][c] : W[k][4c..4c+3]
    __shared__ float4 hsm[32 * 16];  // [node][c]

    int tid = threadIdx.x;
    const float4* W4 = (const float4*)W;
    for (int i = tid; i < F * 16; i += 256) Wsm[i] = W4[i];

    int c = tid & 15;
    int g = tid >> 4;
    int base = blockIdx.x * 32;

    float4 as4 = ((const float4*)a_src)[c];
    float4 ad4 = ((const float4*)a_dst)[c];

    // ---- stage h for 32 nodes ----
    if (first) {
        for (int i = tid; i < 512; i += 256) {
            int node = i >> 4, cc = i & 15;
            int n = base + node;
            float4 v = make_float4(0.f, 0.f, 0.f, 0.f);
            if (n < NN) v = ((const float4*)x)[n * 16 + cc];
            hsm[i] = v;
        }
    } else {
        for (int i = tid; i < 512; i += 256) {
            int node = i >> 4, cc = i & 15;
            int n = base + node;
            float4 v = make_float4(0.f, 0.f, 0.f, 0.f);
            if (n < NN) {
                float dinv = 1.f / g_denom[n];
                float4 a = ((const float4*)g_agg)[n * 16 + cc];
                float4 bb = ((const float4*)bias_prev)[cc];
                v.x = fmaxf(fmaf(a.x, dinv, bb.x), 0.f);
                v.y = fmaxf(fmaf(a.y, dinv, bb.y), 0.f);
                v.z = fmaxf(fmaf(a.z, dinv, bb.z), 0.f);
                v.w = fmaxf(fmaf(a.w, dinv, bb.w), 0.f);
            }
            hsm[i] = v;
        }
    }
    __syncthreads();

    // ---- GEMM: xp[n][f] = sum_k h[n][k] * W[k][f] ----
    float4 acc0 = make_float4(0.f, 0.f, 0.f, 0.f);
    float4 acc1 = make_float4(0.f, 0.f, 0.f, 0.f);
    const float* h0 = (const float*)&hsm[g * 16];
    const float* h1 = (const float*)&hsm[(g + 16) * 16];
#pragma unroll
    for (int k = 0; k < F; ++k) {
        float4 w = Wsm[k * 16 + c];
        float hk0 = h0[k];
        float hk1 = h1[k];
        acc0.x = fmaf(hk0, w.x, acc0.x);
        acc0.y = fmaf(hk0, w.y, acc0.y);
        acc0.z = fmaf(hk0, w.z, acc0.z);
        acc0.w = fmaf(hk0, w.w, acc0.w);
        acc1.x = fmaf(hk1, w.x, acc1.x);
        acc1.y = fmaf(hk1, w.y, acc1.y);
        acc1.z = fmaf(hk1, w.z, acc1.z);
        acc1.w = fmaf(hk1, w.w, acc1.w);
    }

    // ---- attention logits: reduce xp . a_src, xp . a_dst across the 16 lanes ----
    float ps0 = acc0.x * as4.x + acc0.y * as4.y + acc0.z * as4.z + acc0.w * as4.w;
    float pd0 = acc0.x * ad4.x + acc0.y * ad4.y + acc0.z * ad4.z + acc0.w * ad4.w;
    float ps1 = acc1.x * as4.x + acc1.y * as4.y + acc1.z * as4.z + acc1.w * as4.w;
    float pd1 = acc1.x * ad4.x + acc1.y * ad4.y + acc1.z * ad4.z + acc1.w * ad4.w;
#pragma unroll
    for (int o = 1; o < 16; o <<= 1) {
        ps0 += __shfl_xor_sync(0xffffffffu, ps0, o, 16);
        pd0 += __shfl_xor_sync(0xffffffffu, pd0, o, 16);
        ps1 += __shfl_xor_sync(0xffffffffu, ps1, o, 16);
        pd1 += __shfl_xor_sync(0xffffffffu, pd1, o, 16);
    }

    // self-loop term (src == dst == n)
    float e0 = ps0 + pd0; e0 = e0 > 0.f ? e0 : 0.2f * e0; float ex0 = __expf(e0);
    float e1 = ps1 + pd1; e1 = e1 > 0.f ? e1 : 0.2f * e1; float ex1 = __expf(e1);

    int n0 = base + g;
    int n1 = base + g + 16;
    if (n0 < NN) {
        if (c == 0) { g_asrc[n0] = ps0; g_adst[n0] = pd0; g_denom[n0] = ex0; }
        ((float4*)g_xp)[n0 * 16 + c] = acc0;
        float4 t = make_float4(ex0 * acc0.x, ex0 * acc0.y, ex0 * acc0.z, ex0 * acc0.w);
        ((float4*)g_agg)[n0 * 16 + c] = t;
    }
    if (n1 < NN) {
        if (c == 0) { g_asrc[n1] = ps1; g_adst[n1] = pd1; g_denom[n1] = ex1; }
        ((float4*)g_xp)[n1 * 16 + c] = acc1;
        float4 t = make_float4(ex1 * acc1.x, ex1 * acc1.y, ex1 * acc1.z, ex1 * acc1.w);
        ((float4*)g_agg)[n1 * 16 + c] = t;
    }
}

// Edge kernel: 16 threads per edge. lane0 computes exp(leaky(asrc[s]+adst[d])),
// adds to denom[d]; all lanes scatter ex*xp[s] (float4 vector red) into agg[d].
__global__ __launch_bounds__(256) void edge_kernel(
    const int* __restrict__ src, const int* __restrict__ dst)
{
    int gid = blockIdx.x * blockDim.x + threadIdx.x;
    int e = gid >> 4;
    int lane = gid & 15;
    if (e >= NE) return;

    int s = src[e];
    int d = dst[e];

    float ex = 0.f;
    if (lane == 0) {
        float ee = g_asrc[s] + g_adst[d];
        ee = ee > 0.f ? ee : 0.2f * ee;
        ex = __expf(ee);
        atomicAdd(&g_denom[d], ex);
    }
    ex = __shfl_sync(0xffffffffu, ex, 0, 16);

    const float4* xp4 = reinterpret_cast<const float4*>(g_xp);
    float4 v = xp4[s * 16 + lane];
    float* a = g_agg + (d * 16 + lane) * 4;
    red_add_v4(a, ex * v.x, ex * v.y, ex * v.z, ex * v.w);
}

// Pool: h2 = relu(agg/denom + b2); atomic-add into per-graph sums + counts.
__global__ __launch_bounds__(256) void pool_kernel(
    const float* __restrict__ bias, const int* __restrict__ batch)
{
    int gid = blockIdx.x * blockDim.x + threadIdx.x;
    int n = gid >> 4;
    int lane = gid & 15;
    if (n >= NN) return;

    float dinv = 1.f / g_denom[n];
    float4 v = reinterpret_cast<const float4*>(g_agg)[n * 16 + lane];
    float4 b = reinterpret_cast<const float4*>(bias)[lane];
    v.x = fmaxf(fmaf(v.x, dinv, b.x), 0.f);
    v.y = fmaxf(fmaf(v.y, dinv, b.y), 0.f);
    v.z = fmaxf(fmaf(v.z, dinv, b.z), 0.f);
    v.w = fmaxf(fmaf(v.w, dinv, b.w), 0.f);

    int g = batch[n];
    red_add_v4(g_pool + (g * 16 + lane) * 4, v.x, v.y, v.z, v.w);
    if (lane == 0) atomicAdd(&g_cnt[g], 1);
}

__global__ void final_kernel(float* __restrict__ out) {
    int i = blockIdx.x * blockDim.x + threadIdx.x;
    if (i >= NG * F) return;
    int g = i >> 6;
    float c = (float)max(g_cnt[g], 1);
    out[i] = g_pool[i] / c;
}

extern "C" void kernel_launch(void* const* d_in, const int* in_sizes, int n_in,
                              void* d_out, int out_size) {
    const float* x     = (const float*)d_in[0];
    const int*   ei    = (const int*)d_in[1];     // [2, NE]
    const int*   batch = (const int*)d_in[2];
    const float* W1    = (const float*)d_in[3];
    const float* as1   = (const float*)d_in[4];
    const float* ad1   = (const float*)d_in[5];
    const float* b1    = (const float*)d_in[6];
    const float* W2    = (const float*)d_in[7];
    const float* as2   = (const float*)d_in[8];
    const float* ad2   = (const float*)d_in[9];
    const float* b2    = (const float*)d_in[10];
    float* out = (float*)d_out;

    const int* src = ei;
    const int* dst = ei + NE;

    int node_blocks = (NN + 31) / 32;           // 1563
    int edge_blocks = (NE * 16 + 255) / 256;    // 50000
    int pool_blocks = (NN * 16 + 255) / 256;    // 3125

    zero_kernel<<<(NG * F + 255) / 256, 256>>>();

    // layer 1
    node_kernel<<<node_blocks, 256>>>(x, W1, as1, ad1, nullptr, 1);
    edge_kernel<<<edge_blocks, 256>>>(src, dst);

    // layer 2 (reads layer-1 agg/denom, applies b1 + relu, re-inits agg/denom)
    node_kernel<<<node_blocks, 256>>>(nullptr, W2, as2, ad2, b1, 0);
    edge_kernel<<<edge_blocks, 256>>>(src, dst);

    // readout
    pool_kernel<<<pool_blocks, 256>>>(b2, batch);
    final_kernel<<<(NG * F + 255) / 256, 256>>>(out);
}

// round 3
// speedup vs baseline: 1.6093x; 1.2383x over previous
#include <cuda_runtime.h>
#include <cuda_bf16.h>

#define NN 50000
#define NE 800000
#define NG 128
#define F 64
#define CAP 128   // max in-degree stored; deg ~ Poisson(16), P(>128) ~ 0

// ---- scratch (static device arrays; no allocation) ----
__device__ __align__(16) float g_xp[NN * F];    // x @ W  (current layer)
__device__ __align__(16) float g_agg[NN * F];   // self + edge aggregation
__device__ float g_asrc[NN];
__device__ float g_adst[NN];
__device__ float g_denom[NN];
__device__ __align__(16) float g_pool[NG * F];
__device__ int g_gcnt[NG];
__device__ int g_deg[NN];
__device__ int g_csr[NN * CAP];                 // src lists grouped by dst

__device__ __forceinline__ void red_add_v4(float* addr, float a, float b, float c, float d) {
    asm volatile("red.global.add.v4.f32 [%0], {%1,%2,%3,%4};"
                 :: "l"(addr), "f"(a), "f"(b), "f"(c), "f"(d) : "memory");
}

__global__ void zero_kernel() {
    int i = blockIdx.x * blockDim.x + threadIdx.x;
    if (i < NG * F) g_pool[i] = 0.f;
    if (i < NG) g_gcnt[i] = 0;
    if (i < NN) g_deg[i] = 0;
}

// Build by-dst adjacency (fixed capacity). Run once per launch, reused by both layers.
__global__ __launch_bounds__(256) void build_kernel(
    const int* __restrict__ src, const int* __restrict__ dst)
{
    int e = blockIdx.x * blockDim.x + threadIdx.x;
    if (e >= NE) return;
    int d = dst[e];
    int r = atomicAdd(&g_deg[d], 1);
    if (r < CAP) g_csr[d * CAP + r] = src[e];
}

// Node kernel (register-tiled GEMM, 4 nodes/thread):
// 256 threads handle 64 nodes. Thread (g = tid>>4, c = tid&15) computes
// nodes {g, g+16, g+32, g+48}, features [4c, 4c+4).
// hsm padded to stride 65 floats -> broadcast h loads are conflict-free.
__global__ __launch_bounds__(256) void node_kernel(
    const float* __restrict__ x,          // used if first
    const float* __restrict__ W,
    const float* __restrict__ a_src,
    const float* __restrict__ a_dst,
    const float* __restrict__ bias_prev,  // used if !first
    int first)
{
    __shared__ float4 Wsm[F * 16];   // [k][c] : W[k][4c..4c+3]
    __shared__ float hsm[64 * 65];   // [node][k], padded stride 65

    int tid = threadIdx.x;
    const float4* W4 = (const float4*)W;
    for (int i = tid; i < F * 16; i += 256) Wsm[i] = W4[i];

    int c = tid & 15;
    int g = tid >> 4;
    int base = blockIdx.x * 64;

    float4 as4 = ((const float4*)a_src)[c];
    float4 ad4 = ((const float4*)a_dst)[c];

    // ---- stage h for 64 nodes ----
    for (int i = tid; i < 1024; i += 256) {
        int node = i >> 4, cc = i & 15;
        int n = base + node;
        float4 v = make_float4(0.f, 0.f, 0.f, 0.f);
        if (n < NN) {
            if (first) {
                v = ((const float4*)x)[n * 16 + cc];
            } else {
                float dinv = 1.f / g_denom[n];
                float4 a = ((const float4*)g_agg)[n * 16 + cc];
                float4 bb = ((const float4*)bias_prev)[cc];
                v.x = fmaxf(fmaf(a.x, dinv, bb.x), 0.f);
                v.y = fmaxf(fmaf(a.y, dinv, bb.y), 0.f);
                v.z = fmaxf(fmaf(a.z, dinv, bb.z), 0.f);
                v.w = fmaxf(fmaf(a.w, dinv, bb.w), 0.f);
            }
        }
        float* hp = &hsm[node * 65 + cc * 4];
        hp[0] = v.x; hp[1] = v.y; hp[2] = v.z; hp[3] = v.w;
    }
    __syncthreads();

    // ---- GEMM: xp[n][f] = sum_k h[n][k] * W[k][f] ----
    float4 acc0 = make_float4(0.f,0.f,0.f,0.f);
    float4 acc1 = make_float4(0.f,0.f,0.f,0.f);
    float4 acc2 = make_float4(0.f,0.f,0.f,0.f);
    float4 acc3 = make_float4(0.f,0.f,0.f,0.f);
    const float* h0 = &hsm[(g     ) * 65];
    const float* h1 = &hsm[(g + 16) * 65];
    const float* h2 = &hsm[(g + 32) * 65];
    const float* h3 = &hsm[(g + 48) * 65];
#pragma unroll
    for (int k = 0; k < F; ++k) {
        float4 w = Wsm[k * 16 + c];
        float a0 = h0[k], a1 = h1[k], a2 = h2[k], a3 = h3[k];
        acc0.x = fmaf(a0, w.x, acc0.x); acc0.y = fmaf(a0, w.y, acc0.y);
        acc0.z = fmaf(a0, w.z, acc0.z); acc0.w = fmaf(a0, w.w, acc0.w);
        acc1.x = fmaf(a1, w.x, acc1.x); acc1.y = fmaf(a1, w.y, acc1.y);
        acc1.z = fmaf(a1, w.z, acc1.z); acc1.w = fmaf(a1, w.w, acc1.w);
        acc2.x = fmaf(a2, w.x, acc2.x); acc2.y = fmaf(a2, w.y, acc2.y);
        acc2.z = fmaf(a2, w.z, acc2.z); acc2.w = fmaf(a2, w.w, acc2.w);
        acc3.x = fmaf(a3, w.x, acc3.x); acc3.y = fmaf(a3, w.y, acc3.y);
        acc3.z = fmaf(a3, w.z, acc3.z); acc3.w = fmaf(a3, w.w, acc3.w);
    }

    float4 accs[4] = {acc0, acc1, acc2, acc3};
#pragma unroll
    for (int r = 0; r < 4; ++r) {
        float4 a = accs[r];
        float ps = a.x * as4.x + a.y * as4.y + a.z * as4.z + a.w * as4.w;
        float pd = a.x * ad4.x + a.y * ad4.y + a.z * ad4.z + a.w * ad4.w;
#pragma unroll
        for (int o = 1; o < 16; o <<= 1) {
            ps += __shfl_xor_sync(0xffffffffu, ps, o, 16);
            pd += __shfl_xor_sync(0xffffffffu, pd, o, 16);
        }
        // self-loop term (src == dst == n)
        float e = ps + pd; e = e > 0.f ? e : 0.2f * e;
        float ex = __expf(e);
        int n = base + g + 16 * r;
        if (n < NN) {
            if (c == 0) { g_asrc[n] = ps; g_adst[n] = pd; g_denom[n] = ex; }
            ((float4*)g_xp)[n * 16 + c] = a;
            float4 t = make_float4(ex * a.x, ex * a.y, ex * a.z, ex * a.w);
            ((float4*)g_agg)[n * 16 + c] = t;
        }
    }
}

// Aggregation (CSR gather, no float atomics): 16 lanes per dst node.
// Lanes load up to 16 src indices, compute exp weights, then broadcast each
// edge via 16-wide shfl and gather+fma xp[src] (coalesced 256B rows).
__global__ __launch_bounds__(256) void agg_kernel() {
    int gid = blockIdx.x * blockDim.x + threadIdx.x;
    int n = gid >> 4;
    int lane = threadIdx.x & 15;
    unsigned gmask = 0xFFFFu << (threadIdx.x & 16);
    if (n >= NN) return;

    int deg = min(g_deg[n], CAP);
    float adstn = g_adst[n];
    const int* row = &g_csr[n * CAP];
    const float4* xp4 = (const float4*)g_xp;

    float4 acc = make_float4(0.f, 0.f, 0.f, 0.f);
    float dsum = 0.f;

    for (int basee = 0; basee < deg; basee += 16) {
        int j = basee + lane;
        int s = 0; float ex = 0.f;
        if (j < deg) {
            s = row[j];
            float e = g_asrc[s] + adstn;
            e = e > 0.f ? e : 0.2f * e;
            ex = __expf(e);
            dsum += ex;
        }
        int m = min(16, deg - basee);
        for (int i = 0; i < m; ++i) {
            int   si  = __shfl_sync(gmask, s,  i, 16);
            float exi = __shfl_sync(gmask, ex, i, 16);
            float4 v = xp4[si * 16 + lane];
            acc.x = fmaf(exi, v.x, acc.x);
            acc.y = fmaf(exi, v.y, acc.y);
            acc.z = fmaf(exi, v.z, acc.z);
            acc.w = fmaf(exi, v.w, acc.w);
        }
    }
#pragma unroll
    for (int o = 1; o < 16; o <<= 1)
        dsum += __shfl_xor_sync(gmask, dsum, o, 16);

    float4 a = ((float4*)g_agg)[n * 16 + lane];
    a.x += acc.x; a.y += acc.y; a.z += acc.z; a.w += acc.w;
    ((float4*)g_agg)[n * 16 + lane] = a;
    if (lane == 0) g_denom[n] += dsum;
}

// Pool: h2 = relu(agg/denom + b2); atomic-add into per-graph sums + counts.
__global__ __launch_bounds__(256) void pool_kernel(
    const float* __restrict__ bias, const int* __restrict__ batch)
{
    int gid = blockIdx.x * blockDim.x + threadIdx.x;
    int n = gid >> 4;
    int lane = gid & 15;
    if (n >= NN) return;

    float dinv = 1.f / g_denom[n];
    float4 v = reinterpret_cast<const float4*>(g_agg)[n * 16 + lane];
    float4 b = reinterpret_cast<const float4*>(bias)[lane];
    v.x = fmaxf(fmaf(v.x, dinv, b.x), 0.f);
    v.y = fmaxf(fmaf(v.y, dinv, b.y), 0.f);
    v.z = fmaxf(fmaf(v.z, dinv, b.z), 0.f);
    v.w = fmaxf(fmaf(v.w, dinv, b.w), 0.f);

    int g = batch[n];
    red_add_v4(g_pool + (g * 16 + lane) * 4, v.x, v.y, v.z, v.w);
    if (lane == 0) atomicAdd(&g_gcnt[g], 1);
}

__global__ void final_kernel(float* __restrict__ out) {
    int i = blockIdx.x * blockDim.x + threadIdx.x;
    if (i >= NG * F) return;
    int g = i >> 6;
    float c = (float)max(g_gcnt[g], 1);
    out[i] = g_pool[i] / c;
}

extern "C" void kernel_launch(void* const* d_in, const int* in_sizes, int n_in,
                              void* d_out, int out_size) {
    const float* x     = (const float*)d_in[0];
    const int*   ei    = (const int*)d_in[1];     // [2, NE]
    const int*   batch = (const int*)d_in[2];
    const float* W1    = (const float*)d_in[3];
    const float* as1   = (const float*)d_in[4];
    const float* ad1   = (const float*)d_in[5];
    const float* b1    = (const float*)d_in[6];
    const float* W2    = (const float*)d_in[7];
    const float* as2   = (const float*)d_in[8];
    const float* ad2   = (const float*)d_in[9];
    const float* b2    = (const float*)d_in[10];
    float* out = (float*)d_out;

    const int* src = ei;
    const int* dst = ei + NE;

    int node_blocks = (NN + 63) / 64;           // 782
    int agg_blocks  = (NN * 16 + 255) / 256;    // 3125
    int edge_blocks = (NE + 255) / 256;         // 3125

    zero_kernel<<<(NN + 255) / 256, 256>>>();
    build_kernel<<<edge_blocks, 256>>>(src, dst);

    // layer 1
    node_kernel<<<node_blocks, 256>>>(x, W1, as1, ad1, nullptr, 1);
    agg_kernel<<<agg_blocks, 256>>>();

    // layer 2
    node_kernel<<<node_blocks, 256>>>(nullptr, W2, as2, ad2, b1, 0);
    agg_kernel<<<agg_blocks, 256>>>();

    // readout
    pool_kernel<<<agg_blocks, 256>>>(b2, batch);
    final_kernel<<<(NG * F + 255) / 256, 256>>>(out);
}

// round 5
// speedup vs baseline: 1.8534x; 1.1516x over previous
#include <cuda_runtime.h>
#include <cuda_bf16.h>

#define NN 50000
#define NE 800000
#define NG 128
#define F 64
#define CAP 128   // max stored in-degree; deg ~ Poisson(16), P(>128) ~ 0

// ---- scratch (static device arrays; no allocation) ----
__device__ __align__(16) float g_xp[NN * F];    // x @ W (current layer)
__device__ __align__(16) float g_h[NN * F];     // finalized layer output
__device__ float g_asrc[NN];
__device__ float g_adst[NN];
__device__ float g_denom[NN];                   // self-loop exp
__device__ __align__(16) float g_pool[NG * F];
__device__ int g_gcnt[NG];
__device__ int g_deg[NN];
__device__ int g_csr[NN * CAP];                 // src lists grouped by dst

__device__ __forceinline__ void red_add_v4(float* addr, float a, float b, float c, float d) {
    asm volatile("red.global.add.v4.f32 [%0], {%1,%2,%3,%4};"
                 :: "l"(addr), "f"(a), "f"(b), "f"(c), "f"(d) : "memory");
}

__global__ void zero_kernel() {
    int i = blockIdx.x * blockDim.x + threadIdx.x;
    if (i < NG * F) g_pool[i] = 0.f;
    if (i < NG) g_gcnt[i] = 0;
    if (i < NN) g_deg[i] = 0;
}

// Build by-dst adjacency + per-graph node counts. Once per launch.
__global__ __launch_bounds__(256) void build_kernel(
    const int* __restrict__ src, const int* __restrict__ dst,
    const int* __restrict__ batch)
{
    int e = blockIdx.x * blockDim.x + threadIdx.x;
    if (e < NN) atomicAdd(&g_gcnt[batch[e]], 1);
    if (e >= NE) return;
    int d = dst[e];
    int r = atomicAdd(&g_deg[d], 1);
    if (r < CAP) g_csr[d * CAP + r] = src[e];
}

// Node kernel (register-tiled GEMM, 4 nodes/thread):
// 256 threads handle 64 nodes. Thread (g = tid>>4, c = tid&15) computes
// nodes {g, g+16, g+32, g+48}, features [4c, 4c+4).
// Writes xp, asrc, adst, denom(=self-loop exp). agg reconstructs the self term.
__global__ __launch_bounds__(256) void node_kernel(
    const float* __restrict__ x,          // used if use_x
    const float* __restrict__ W,
    const float* __restrict__ a_src,
    const float* __restrict__ a_dst,
    int use_x)                            // else read finalized g_h
{
    __shared__ float4 Wsm[F * 16];   // [k][c] : W[k][4c..4c+3]
    __shared__ float hsm[64 * 65];   // [node][k], padded stride 65

    int tid = threadIdx.x;
    const float4* W4 = (const float4*)W;
    for (int i = tid; i < F * 16; i += 256) Wsm[i] = W4[i];

    int c = tid & 15;
    int g = tid >> 4;
    int base = blockIdx.x * 64;

    float4 as4 = ((const float4*)a_src)[c];
    float4 ad4 = ((const float4*)a_dst)[c];

    // ---- stage h for 64 nodes ----
    const float4* hin = use_x ? (const float4*)x : (const float4*)g_h;
    for (int i = tid; i < 1024; i += 256) {
        int node = i >> 4, cc = i & 15;
        int n = base + node;
        float4 v = make_float4(0.f, 0.f, 0.f, 0.f);
        if (n < NN) v = hin[n * 16 + cc];
        float* hp = &hsm[node * 65 + cc * 4];
        hp[0] = v.x; hp[1] = v.y; hp[2] = v.z; hp[3] = v.w;
    }
    __syncthreads();

    // ---- GEMM: xp[n][f] = sum_k h[n][k] * W[k][f] ----
    float4 acc0 = make_float4(0.f,0.f,0.f,0.f);
    float4 acc1 = make_float4(0.f,0.f,0.f,0.f);
    float4 acc2 = make_float4(0.f,0.f,0.f,0.f);
    float4 acc3 = make_float4(0.f,0.f,0.f,0.f);
    const float* h0 = &hsm[(g     ) * 65];
    const float* h1 = &hsm[(g + 16) * 65];
    const float* h2 = &hsm[(g + 32) * 65];
    const float* h3 = &hsm[(g + 48) * 65];
#pragma unroll
    for (int k = 0; k < F; ++k) {
        float4 w = Wsm[k * 16 + c];
        float a0 = h0[k], a1 = h1[k], a2 = h2[k], a3 = h3[k];
        acc0.x = fmaf(a0, w.x, acc0.x); acc0.y = fmaf(a0, w.y, acc0.y);
        acc0.z = fmaf(a0, w.z, acc0.z); acc0.w = fmaf(a0, w.w, acc0.w);
        acc1.x = fmaf(a1, w.x, acc1.x); acc1.y = fmaf(a1, w.y, acc1.y);
        acc1.z = fmaf(a1, w.z, acc1.z); acc1.w = fmaf(a1, w.w, acc1.w);
        acc2.x = fmaf(a2, w.x, acc2.x); acc2.y = fmaf(a2, w.y, acc2.y);
        acc2.z = fmaf(a2, w.z, acc2.z); acc2.w = fmaf(a2, w.w, acc2.w);
        acc3.x = fmaf(a3, w.x, acc3.x); acc3.y = fmaf(a3, w.y, acc3.y);
        acc3.z = fmaf(a3, w.z, acc3.z); acc3.w = fmaf(a3, w.w, acc3.w);
    }

    float4 accs[4] = {acc0, acc1, acc2, acc3};
#pragma unroll
    for (int r = 0; r < 4; ++r) {
        float4 a = accs[r];
        float ps = a.x * as4.x + a.y * as4.y + a.z * as4.z + a.w * as4.w;
        float pd = a.x * ad4.x + a.y * ad4.y + a.z * ad4.z + a.w * ad4.w;
#pragma unroll
        for (int o = 1; o < 16; o <<= 1) {
            ps += __shfl_xor_sync(0xffffffffu, ps, o, 16);
            pd += __shfl_xor_sync(0xffffffffu, pd, o, 16);
        }
        int n = base + g + 16 * r;
        if (n < NN) {
            if (c == 0) {
                g_asrc[n] = ps; g_adst[n] = pd;
                float e = ps + pd; e = e > 0.f ? e : 0.2f * e;   // self-loop logit
                g_denom[n] = __expf(e);
            }
            ((float4*)g_xp)[n * 16 + c] = a;
        }
    }
}

// Aggregation + epilogue (CSR gather, no float atomics): 16 lanes per dst node.
// Predicated fully-unrolled inner loop -> up to 16 independent LDG.128 in flight.
// FINAL=0: write h = relu(total/denom + bias) to g_h.
// FINAL=1: graph-mean pool via red.v4 into g_pool.
template<int FINAL>
__global__ __launch_bounds__(256) void agg_kernel(
    const float* __restrict__ bias, const int* __restrict__ batch)
{
    int gid = blockIdx.x * blockDim.x + threadIdx.x;
    int n = gid >> 4;
    int lane = threadIdx.x & 15;
    unsigned gmask = 0xFFFFu << (threadIdx.x & 16);
    if (n >= NN) return;

    int deg = min(g_deg[n], CAP);
    float adstn = g_adst[n];
    float ex_self = g_denom[n];
    const int* row = &g_csr[n * CAP];
    const float4* xp4 = (const float4*)g_xp;

    // self-loop feature contribution (per-lane feature slice; weight added ONCE below)
    float4 selfv = xp4[n * 16 + lane];
    float4 acc = make_float4(ex_self * selfv.x, ex_self * selfv.y,
                             ex_self * selfv.z, ex_self * selfv.w);
    float dsum = 0.f;   // edge weights only; ex_self added once after lane-reduction

    for (int basee = 0; basee < deg; basee += 16) {
        int j = basee + lane;
        int s = 0; float ex = 0.f;
        if (j < deg) {
            s = row[j];
            float e = g_asrc[s] + adstn;
            e = e > 0.f ? e : 0.2f * e;
            ex = __expf(e);
            dsum += ex;
        }
#pragma unroll
        for (int i = 0; i < 16; ++i) {
            int   si  = __shfl_sync(gmask, s,  i, 16);
            float exi = __shfl_sync(gmask, ex, i, 16);
            float4 v = xp4[si * 16 + lane];
            acc.x = fmaf(exi, v.x, acc.x);
            acc.y = fmaf(exi, v.y, acc.y);
            acc.z = fmaf(exi, v.z, acc.z);
            acc.w = fmaf(exi, v.w, acc.w);
        }
    }
#pragma unroll
    for (int o = 1; o < 16; o <<= 1)
        dsum += __shfl_xor_sync(gmask, dsum, o, 16);
    dsum += ex_self;    // self weight counted exactly once

    float dinv = 1.f / dsum;
    float4 b = ((const float4*)bias)[lane];
    float4 h;
    h.x = fmaxf(fmaf(acc.x, dinv, b.x), 0.f);
    h.y = fmaxf(fmaf(acc.y, dinv, b.y), 0.f);
    h.z = fmaxf(fmaf(acc.z, dinv, b.z), 0.f);
    h.w = fmaxf(fmaf(acc.w, dinv, b.w), 0.f);

    if (FINAL) {
        int g = batch[n];
        red_add_v4(g_pool + (g * 16 + lane) * 4, h.x, h.y, h.z, h.w);
    } else {
        ((float4*)g_h)[n * 16 + lane] = h;
    }
}

__global__ void final_kernel(float* __restrict__ out) {
    int i = blockIdx.x * blockDim.x + threadIdx.x;
    if (i >= NG * F) return;
    int g = i >> 6;
    float c = (float)max(g_gcnt[g], 1);
    out[i] = g_pool[i] / c;
}

extern "C" void kernel_launch(void* const* d_in, const int* in_sizes, int n_in,
                              void* d_out, int out_size) {
    const float* x     = (const float*)d_in[0];
    const int*   ei    = (const int*)d_in[1];     // [2, NE]
    const int*   batch = (const int*)d_in[2];
    const float* W1    = (const float*)d_in[3];
    const float* as1   = (const float*)d_in[4];
    const float* ad1   = (const float*)d_in[5];
    const float* b1    = (const float*)d_in[6];
    const float* W2    = (const float*)d_in[7];
    const float* as2   = (const float*)d_in[8];
    const float* ad2   = (const float*)d_in[9];
    const float* b2    = (const float*)d_in[10];
    float* out = (float*)d_out;

    const int* src = ei;
    const int* dst = ei + NE;

    int node_blocks = (NN + 63) / 64;           // 782
    int agg_blocks  = (NN * 16 + 255) / 256;    // 3125
    int edge_blocks = (NE + 255) / 256;         // 3125

    zero_kernel<<<(NN + 255) / 256, 256>>>();
    build_kernel<<<edge_blocks, 256>>>(src, dst, batch);

    // layer 1
    node_kernel<<<node_blocks, 256>>>(x, W1, as1, ad1, 1);
    agg_kernel<0><<<agg_blocks, 256>>>(b1, batch);

    // layer 2 (agg fuses relu+bias+graph-pool)
    node_kernel<<<node_blocks, 256>>>(nullptr, W2, as2, ad2, 0);
    agg_kernel<1><<<agg_blocks, 256>>>(b2, batch);

    final_kernel<<<(NG * F + 255) / 256, 256>>>(out);
}

// round 6
// speedup vs baseline: 1.9382x; 1.0457x over previous
#include <cuda_runtime.h>
#include <cuda_bf16.h>

#define NN 50000
#define NE 800000
#define NG 128
#define F 64
#define CAP 128   // max stored in-degree; deg ~ Poisson(16), P(>128) ~ 0

// ---- scratch (static device arrays; no allocation) ----
__device__ __align__(16) float g_xp[NN * F];    // x @ W (current layer)
__device__ __align__(16) float g_h[NN * F];     // finalized layer output
__device__ float g_asrc[NN];
__device__ float g_adst[NN];
__device__ float g_denom[NN];                   // self-loop exp
__device__ __align__(16) float g_pool[NG * F];
__device__ int g_gcnt[NG];
__device__ int g_deg[NN];
__device__ int g_csr[NN * CAP];                 // src lists grouped by dst

__device__ __forceinline__ void red_add_v4(float* addr, float a, float b, float c, float d) {
    asm volatile("red.global.add.v4.f32 [%0], {%1,%2,%3,%4};"
                 :: "l"(addr), "f"(a), "f"(b), "f"(c), "f"(d) : "memory");
}

__global__ void zero_kernel() {
    int i = blockIdx.x * blockDim.x + threadIdx.x;
    if (i < NG * F) g_pool[i] = 0.f;
    if (i < NG) g_gcnt[i] = 0;
    if (i < NN) g_deg[i] = 0;
}

// Build by-dst adjacency + per-graph node counts. Once per launch.
__global__ __launch_bounds__(256) void build_kernel(
    const int* __restrict__ src, const int* __restrict__ dst,
    const int* __restrict__ batch)
{
    int e = blockIdx.x * blockDim.x + threadIdx.x;
    if (e < NN) atomicAdd(&g_gcnt[batch[e]], 1);
    if (e >= NE) return;
    int d = dst[e];
    int r = atomicAdd(&g_deg[d], 1);
    if (r < CAP) g_csr[d * CAP + r] = src[e];
}

// Node kernel (register-tiled GEMM, 4 nodes/thread):
// 256 threads handle 64 nodes. Thread (g = tid>>4, c = tid&15) computes
// nodes {g, g+16, g+32, g+48}, features [4c, 4c+4).
__global__ __launch_bounds__(256) void node_kernel(
    const float* __restrict__ x,          // used if use_x
    const float* __restrict__ W,
    const float* __restrict__ a_src,
    const float* __restrict__ a_dst,
    int use_x)                            // else read finalized g_h
{
    __shared__ float4 Wsm[F * 16];   // [k][c] : W[k][4c..4c+3]
    __shared__ float hsm[64 * 65];   // [node][k], padded stride 65

    int tid = threadIdx.x;
    const float4* W4 = (const float4*)W;
    for (int i = tid; i < F * 16; i += 256) Wsm[i] = W4[i];

    int c = tid & 15;
    int g = tid >> 4;
    int base = blockIdx.x * 64;

    float4 as4 = ((const float4*)a_src)[c];
    float4 ad4 = ((const float4*)a_dst)[c];

    // ---- stage h for 64 nodes ----
    const float4* hin = use_x ? (const float4*)x : (const float4*)g_h;
    for (int i = tid; i < 1024; i += 256) {
        int node = i >> 4, cc = i & 15;
        int n = base + node;
        float4 v = make_float4(0.f, 0.f, 0.f, 0.f);
        if (n < NN) v = hin[n * 16 + cc];
        float* hp = &hsm[node * 65 + cc * 4];
        hp[0] = v.x; hp[1] = v.y; hp[2] = v.z; hp[3] = v.w;
    }
    __syncthreads();

    // ---- GEMM: xp[n][f] = sum_k h[n][k] * W[k][f] ----
    float4 acc0 = make_float4(0.f,0.f,0.f,0.f);
    float4 acc1 = make_float4(0.f,0.f,0.f,0.f);
    float4 acc2 = make_float4(0.f,0.f,0.f,0.f);
    float4 acc3 = make_float4(0.f,0.f,0.f,0.f);
    const float* h0 = &hsm[(g     ) * 65];
    const float* h1 = &hsm[(g + 16) * 65];
    const float* h2 = &hsm[(g + 32) * 65];
    const float* h3 = &hsm[(g + 48) * 65];
#pragma unroll
    for (int k = 0; k < F; ++k) {
        float4 w = Wsm[k * 16 + c];
        float a0 = h0[k], a1 = h1[k], a2 = h2[k], a3 = h3[k];
        acc0.x = fmaf(a0, w.x, acc0.x); acc0.y = fmaf(a0, w.y, acc0.y);
        acc0.z = fmaf(a0, w.z, acc0.z); acc0.w = fmaf(a0, w.w, acc0.w);
        acc1.x = fmaf(a1, w.x, acc1.x); acc1.y = fmaf(a1, w.y, acc1.y);
        acc1.z = fmaf(a1, w.z, acc1.z); acc1.w = fmaf(a1, w.w, acc1.w);
        acc2.x = fmaf(a2, w.x, acc2.x); acc2.y = fmaf(a2, w.y, acc2.y);
        acc2.z = fmaf(a2, w.z, acc2.z); acc2.w = fmaf(a2, w.w, acc2.w);
        acc3.x = fmaf(a3, w.x, acc3.x); acc3.y = fmaf(a3, w.y, acc3.y);
        acc3.z = fmaf(a3, w.z, acc3.z); acc3.w = fmaf(a3, w.w, acc3.w);
    }

    float4 accs[4] = {acc0, acc1, acc2, acc3};
#pragma unroll
    for (int r = 0; r < 4; ++r) {
        float4 a = accs[r];
        float ps = a.x * as4.x + a.y * as4.y + a.z * as4.z + a.w * as4.w;
        float pd = a.x * ad4.x + a.y * ad4.y + a.z * ad4.z + a.w * ad4.w;
#pragma unroll
        for (int o = 1; o < 16; o <<= 1) {
            ps += __shfl_xor_sync(0xffffffffu, ps, o, 16);
            pd += __shfl_xor_sync(0xffffffffu, pd, o, 16);
        }
        int n = base + g + 16 * r;
        if (n < NN) {
            if (c == 0) {
                g_asrc[n] = ps; g_adst[n] = pd;
                float e = ps + pd; e = e > 0.f ? e : 0.2f * e;   // self-loop logit
                g_denom[n] = __expf(e);
            }
            ((float4*)g_xp)[n * 16 + c] = a;
        }
    }
}

// Aggregation + epilogue: 16 lanes per dst node, 16 nodes per 256-thread block.
// Phase A: lanes compute (src, ex) for all edges, stage in smem (float2).
// Phase B: batches of 8 edges -> 8 independent LDG.128 in flight per thread.
// FINAL=0: write h = relu(total/denom + bias) to g_h.
// FINAL=1: graph-mean pool via red.v4 into g_pool.
template<int FINAL>
__global__ __launch_bounds__(256) void agg_kernel(
    const float* __restrict__ bias, const int* __restrict__ batch)
{
    __shared__ float2 stage[16][CAP];   // [group][edge] = (bitcast src, ex)

    int gid = blockIdx.x * blockDim.x + threadIdx.x;
    int n = gid >> 4;
    int grp = threadIdx.x >> 4;         // 0..15
    int lane = threadIdx.x & 15;
    unsigned gmask = 0xFFFFu << (threadIdx.x & 16);
    if (n >= NN) return;

    int deg = min(g_deg[n], CAP);
    float adstn = g_adst[n];
    float ex_self = g_denom[n];
    const int* row = &g_csr[n * CAP];
    const float4* xp4 = (const float4*)g_xp;

    // ---- Phase A: stage (src, ex), accumulate per-lane dsum ----
    float dsum = 0.f;
    for (int j = lane; j < deg; j += 16) {
        int s = row[j];
        float e = g_asrc[s] + adstn;
        e = e > 0.f ? e : 0.2f * e;
        float ex = __expf(e);
        dsum += ex;
        stage[grp][j] = make_float2(__int_as_float(s), ex);
    }
    __syncwarp();

    // self-loop feature contribution (weight added once after lane-reduction)
    float4 selfv = xp4[n * 16 + lane];
    float4 acc = make_float4(ex_self * selfv.x, ex_self * selfv.y,
                             ex_self * selfv.z, ex_self * selfv.w);

    // ---- Phase B: batched gather (8 independent loads in flight) ----
    for (int j0 = 0; j0 < deg; j0 += 8) {
        float2 e[8];
#pragma unroll
        for (int i = 0; i < 8; ++i) {
            int jj = j0 + i < deg ? j0 + i : 0;   // clamp; weight zeroed below
            e[i] = stage[grp][jj];
            if (j0 + i >= deg) e[i].y = 0.f;
        }
        float4 v[8];
#pragma unroll
        for (int i = 0; i < 8; ++i)
            v[i] = xp4[__float_as_int(e[i].x) * 16 + lane];
#pragma unroll
        for (int i = 0; i < 8; ++i) {
            acc.x = fmaf(e[i].y, v[i].x, acc.x);
            acc.y = fmaf(e[i].y, v[i].y, acc.y);
            acc.z = fmaf(e[i].y, v[i].z, acc.z);
            acc.w = fmaf(e[i].y, v[i].w, acc.w);
        }
    }

#pragma unroll
    for (int o = 1; o < 16; o <<= 1)
        dsum += __shfl_xor_sync(gmask, dsum, o, 16);
    dsum += ex_self;    // self weight counted exactly once

    float dinv = 1.f / dsum;
    float4 b = ((const float4*)bias)[lane];
    float4 h;
    h.x = fmaxf(fmaf(acc.x, dinv, b.x), 0.f);
    h.y = fmaxf(fmaf(acc.y, dinv, b.y), 0.f);
    h.z = fmaxf(fmaf(acc.z, dinv, b.z), 0.f);
    h.w = fmaxf(fmaf(acc.w, dinv, b.w), 0.f);

    if (FINAL) {
        int g = batch[n];
        red_add_v4(g_pool + (g * 16 + lane) * 4, h.x, h.y, h.z, h.w);
    } else {
        ((float4*)g_h)[n * 16 + lane] = h;
    }
}

__global__ void final_kernel(float* __restrict__ out) {
    int i = blockIdx.x * blockDim.x + threadIdx.x;
    if (i >= NG * F) return;
    int g = i >> 6;
    float c = (float)max(g_gcnt[g], 1);
    out[i] = g_pool[i] / c;
}

extern "C" void kernel_launch(void* const* d_in, const int* in_sizes, int n_in,
                              void* d_out, int out_size) {
    const float* x     = (const float*)d_in[0];
    const int*   ei    = (const int*)d_in[1];     // [2, NE]
    const int*   batch = (const int*)d_in[2];
    const float* W1    = (const float*)d_in[3];
    const float* as1   = (const float*)d_in[4];
    const float* ad1   = (const float*)d_in[5];
    const float* b1    = (const float*)d_in[6];
    const float* W2    = (const float*)d_in[7];
    const float* as2   = (const float*)d_in[8];
    const float* ad2   = (const float*)d_in[9];
    const float* b2    = (const float*)d_in[10];
    float* out = (float*)d_out;

    const int* src = ei;
    const int* dst = ei + NE;

    int node_blocks = (NN + 63) / 64;           // 782
    int agg_blocks  = (NN * 16 + 255) / 256;    // 3125
    int edge_blocks = (NE + 255) / 256;         // 3125

    zero_kernel<<<(NN + 255) / 256, 256>>>();
    build_kernel<<<edge_blocks, 256>>>(src, dst, batch);

    // layer 1
    node_kernel<<<node_blocks, 256>>>(x, W1, as1, ad1, 1);
    agg_kernel<0><<<agg_blocks, 256>>>(b1, batch);

    // layer 2 (agg fuses relu+bias+graph-pool)
    node_kernel<<<node_blocks, 256>>>(nullptr, W2, as2, ad2, 0);
    agg_kernel<1><<<agg_blocks, 256>>>(b2, batch);

    final_kernel<<<(NG * F + 255) / 256, 256>>>(out);
}